// round 8
// baseline (speedup 1.0000x reference)
#include <cuda_runtime.h>

// Problem constants (shapes fixed by the dataset)
#define NB   16
#define C    256
#define HW   16384          // 128*128
#define CLS  9
#define P    (NB*HW)        // 262144 pixels
#define NT   256
#define NBLK_ARG ((P/2)/NT) // 512 argmax blocks (2 px/thread)
#define NCHUNK (NB*C*2)     // 8192 half-plane accum blocks
#define ITERS  8            // float4 groups/thread/chunk: 2048/256

// Scratch (no allocation; every word fully overwritten each replay)
__device__ unsigned char g_labels[P];
__device__ int           g_cnt_part[NBLK_ARG * CLS];
__device__ float         g_part[NCHUNK * CLS];

// ---------------------------------------------------------------------------
// 1) per-pixel argmax (float2, 2 px/thread) -> labels + per-block counts
// ---------------------------------------------------------------------------
__global__ void __launch_bounds__(NT) argmax_kernel(const float* __restrict__ logit) {
    __shared__ int s_cnt[CLS];
    const int tid = threadIdx.x;
    if (tid < CLS) s_cnt[tid] = 0;
    __syncthreads();

    const int g   = blockIdx.x * NT + tid;   // float2-group index
    const int n   = g >> 13;                 // g / (HW/2)
    const int hw2 = g & 8191;

    const float2* lp = (const float2*)logit;
    float2 best = lp[(size_t)(n*CLS + 0) * (HW/2) + hw2];
    int lx = 0, ly = 0;
    #pragma unroll
    for (int cls = 1; cls < CLS; cls++) {
        float2 v = lp[(size_t)(n*CLS + cls) * (HW/2) + hw2];
        if (v.x > best.x) { best.x = v.x; lx = cls; }
        if (v.y > best.y) { best.y = v.y; ly = cls; }
    }
    g_labels[2*g]   = (unsigned char)lx;
    g_labels[2*g+1] = (unsigned char)ly;

    atomicAdd(&s_cnt[lx], 1);
    atomicAdd(&s_cnt[ly], 1);
    __syncthreads();
    if (tid < CLS) g_cnt_part[blockIdx.x * CLS + tid] = s_cnt[tid];
}

// ---------------------------------------------------------------------------
// 2) accumulate: one block per half-plane chunk (8192 blocks, ~1% tail).
//    TWO provably-disjoint smem accumulator arrays break the false
//    LDS->FADD->STS serialization: {x,z}->acc0, {y,w}->acc1 run as two
//    parallel RMW chains instead of one 4-deep chain.
// ---------------------------------------------------------------------------
__global__ void __launch_bounds__(NT) accum_kernel(const float* __restrict__ feat) {
    __shared__ float acc0[CLS * NT];
    __shared__ float acc1[CLS * NT];
    __shared__ float s_warp[CLS * 8];
    const int tid = threadIdx.x;
    #pragma unroll
    for (int l = 0; l < CLS; l++) {
        acc0[l*NT + tid] = 0.0f;
        acc1[l*NT + tid] = 0.0f;
    }
    __syncthreads();

    const int chunk = blockIdx.x;        // 0..NCHUNK-1
    const int nc    = chunk >> 1;
    const int half  = chunk & 1;
    const int n     = nc >> 8;

    const float4* fp = (const float4*)feat     + (size_t)nc * 4096 + half * 2048;
    const uchar4* lp = (const uchar4*)g_labels + (size_t)n  * 4096 + half * 2048;

    #pragma unroll
    for (int k = 0; k < ITERS; k++) {
        const int i = tid + k*NT;
        float4 v = fp[i];
        uchar4 l = lp[i];
        acc0[l.x*NT + tid] += v.x;     // chain A
        acc1[l.y*NT + tid] += v.y;     // chain B (disjoint array)
        acc0[l.z*NT + tid] += v.z;     // chain A
        acc1[l.w*NT + tid] += v.w;     // chain B
    }
    __syncthreads();

    // butterfly reduce (merge the two arrays on read)
    float s[CLS];
    #pragma unroll
    for (int c = 0; c < CLS; c++) s[c] = acc0[c*NT + tid] + acc1[c*NT + tid];
    #pragma unroll
    for (int off = 16; off > 0; off >>= 1) {
        #pragma unroll
        for (int c = 0; c < CLS; c++)
            s[c] += __shfl_xor_sync(0xFFFFFFFFu, s[c], off);
    }
    const int warp = tid >> 5, lane = tid & 31;
    if (lane == 0) {
        #pragma unroll
        for (int c = 0; c < CLS; c++) s_warp[c*8 + warp] = s[c];
    }
    __syncthreads();

    if (tid < CLS) {
        float t = 0.0f;
        #pragma unroll
        for (int w = 0; w < 8; w++) t += s_warp[tid*8 + w];
        g_part[chunk*CLS + tid] = t;     // plain store, private slot
    }
}

// ---------------------------------------------------------------------------
// 3) finalize: 9 blocks x 256 threads. Each thread owns one (ch,cls) pair:
//    sum 32 L2-resident partials, scale by 1/count, broadcast over batch.
// ---------------------------------------------------------------------------
__global__ void __launch_bounds__(NT) out_kernel(float* __restrict__ out) {
    __shared__ float s_wcnt[CLS * 8];
    __shared__ float s_inv[CLS];
    const int tid = threadIdx.x;

    float c[CLS];
    #pragma unroll
    for (int l = 0; l < CLS; l++)
        c[l] = (float)g_cnt_part[tid*CLS + l]
             + (float)g_cnt_part[(tid + NT)*CLS + l];
    #pragma unroll
    for (int off = 16; off > 0; off >>= 1) {
        #pragma unroll
        for (int l = 0; l < CLS; l++)
            c[l] += __shfl_xor_sync(0xFFFFFFFFu, c[l], off);
    }
    const int warp = tid >> 5, lane = tid & 31;
    if (lane == 0) {
        #pragma unroll
        for (int l = 0; l < CLS; l++) s_wcnt[l*8 + warp] = c[l];
    }
    __syncthreads();
    if (tid < CLS) {
        float s = 0.0f;
        #pragma unroll
        for (int w = 0; w < 8; w++) s += s_wcnt[tid*8 + w];
        s_inv[tid] = 1.0f / fmaxf(s, 1.0f);
    }
    __syncthreads();

    const int idx = blockIdx.x * NT + tid;   // 0..2303 (C*CLS)
    if (idx >= C*CLS) return;
    const int ch  = idx / CLS;
    const int cls = idx - ch*CLS;

    float s = 0.0f;
    #pragma unroll
    for (int n = 0; n < NB; n++) {
        const int base = ((n*C + ch) * 2) * CLS + cls;
        s += g_part[base] + g_part[base + CLS];
    }
    const float val = s * s_inv[cls];
    #pragma unroll
    for (int n = 0; n < NB; n++)
        out[n*(C*CLS) + idx] = val;
}

// ---------------------------------------------------------------------------
extern "C" void kernel_launch(void* const* d_in, const int* in_sizes, int n_in,
                              void* d_out, int out_size) {
    const float* feat  = (const float*)d_in[0];
    const float* logit = (const float*)d_in[1];
    float* out = (float*)d_out;

    argmax_kernel<<<NBLK_ARG, NT>>>(logit);          // 512 blocks
    accum_kernel<<<NCHUNK, NT>>>(feat);              // 8192 blocks
    out_kernel<<<(C*CLS + NT - 1)/NT, NT>>>(out);    // 9 blocks
}